// round 2
// baseline (speedup 1.0000x reference)
#include <cuda_runtime.h>
#include <cstdint>
#include <math.h>

#define N_NODES 50000
#define N_EDGES 800000
#define XD      128
#define HID     128
#define INCH    256   // XD + HID
#define OUTCH   128

// Scratch: per-node edge feature sums (25.6 MB). __device__ global (no allocs allowed).
__device__ float g_edge_sum[(size_t)N_NODES * HID];

// ---------------------------------------------------------------------------
// Kernel 1: zero the accumulator (graph replays -> must re-zero every launch)
// ---------------------------------------------------------------------------
__global__ void zero_kernel() {
    const size_t n4 = (size_t)N_NODES * HID / 4;
    float4* p = reinterpret_cast<float4*>(g_edge_sum);
    for (size_t i = (size_t)blockIdx.x * blockDim.x + threadIdx.x; i < n4;
         i += (size_t)gridDim.x * blockDim.x) {
        p[i] = make_float4(0.f, 0.f, 0.f, 0.f);
    }
}

// ---------------------------------------------------------------------------
// Kernel 2: scatter-add edge_attr rows into g_edge_sum[src].
// One warp per edge: lane l handles channels [4l, 4l+4) via red.global.v4.f32.
// NOTE: edge_index is INT32 (JAX silently downcasts int64 without x64 mode).
// ---------------------------------------------------------------------------
__global__ void scatter_kernel(const float* __restrict__ edge_attr,
                               const int* __restrict__ edge_src) {
    const int warp = (blockIdx.x * blockDim.x + threadIdx.x) >> 5;
    const int lane = threadIdx.x & 31;
    if (warp >= N_EDGES) return;
    const int src = edge_src[warp];                // broadcast load, row 0 of edge_index
    const float4 v = reinterpret_cast<const float4*>(edge_attr + (size_t)warp * HID)[lane];
    float* dst = g_edge_sum + (size_t)src * HID + lane * 4;
    asm volatile("red.global.add.v4.f32 [%0], {%1,%2,%3,%4};"
                 :: "l"(dst), "f"(v.x), "f"(v.y), "f"(v.z), "f"(v.w)
                 : "memory");
}

// ---------------------------------------------------------------------------
// Kernel 3: fused 3-layer MLP.
//   inputs = [x | edge_sum]  (K=256)
//   h0 = ELU(inputs @ W0 + b0)   -> SMEM
//   h1 = ELU(h0 @ W2 + b2)       -> SMEM (overwrites h0)
//   out = h1 @ W3 + b3           -> GMEM
// Tile: 128 nodes x 128 cols per CTA, 256 threads, each thread an 8x8 micro-tile.
// SMEM: Hs[128][132] (padded) + As[128][36] + Bs[32][128] = 100 KB dynamic.
// ---------------------------------------------------------------------------
#define HS_LD 132   // padded row length for Hs (multiple of 4, breaks 128-stride conflicts)
#define AS_LD 36    // padded row length for As
#define SMEM_FLOATS (128*HS_LD + 128*AS_LD + 32*128)

__global__ __launch_bounds__(256, 2)
void mlp_kernel(const float* __restrict__ x,
                const float* __restrict__ W0, const float* __restrict__ b0,
                const float* __restrict__ W2, const float* __restrict__ b2,
                const float* __restrict__ W3, const float* __restrict__ b3,
                float* __restrict__ out) {
    extern __shared__ float sm[];
    float* Hs = sm;                       // 128 * 132
    float* As = sm + 128 * HS_LD;         // 128 * 36
    float* Bs = As + 128 * AS_LD;         // 32 * 128

    const int tid = threadIdx.x;
    const int tx = tid & 15;              // 16 cols of threads
    const int ty = tid >> 4;              // 16 rows of threads
    const int row0 = ty * 8;              // node within tile
    const int col0 = tx * 8;              // output channel
    const int nodeBase = blockIdx.x * 128;

    float c[8][8];

    // ================= Layer 0: [128 x 256] @ [256 x 128] =================
#pragma unroll
    for (int i = 0; i < 8; i++)
#pragma unroll
        for (int j = 0; j < 8; j++) c[i][j] = 0.f;

    for (int k0 = 0; k0 < INCH; k0 += 32) {
        const float* src = (k0 < XD) ? x : g_edge_sum;
        const int kcol = k0 & (XD - 1);
        // Stage A chunk [128 nodes x 32 k] -> As (row-major, padded)
#pragma unroll
        for (int l = tid; l < 1024; l += 256) {
            const int node = l >> 3, k4 = l & 7;
            float4 v = make_float4(0.f, 0.f, 0.f, 0.f);
            const int gn = nodeBase + node;
            if (gn < N_NODES)
                v = *reinterpret_cast<const float4*>(src + (size_t)gn * 128 + kcol + k4 * 4);
            *reinterpret_cast<float4*>(As + node * AS_LD + k4 * 4) = v;
        }
        // Stage B chunk [32 k x 128 cols] -> Bs
#pragma unroll
        for (int l = tid; l < 1024; l += 256) {
            const int kr = l >> 5, c4 = l & 31;
            *reinterpret_cast<float4*>(Bs + kr * 128 + c4 * 4) =
                *reinterpret_cast<const float4*>(W0 + (size_t)(k0 + kr) * 128 + c4 * 4);
        }
        __syncthreads();
#pragma unroll
        for (int kk = 0; kk < 32; kk++) {
            float a[8], b[8];
#pragma unroll
            for (int i = 0; i < 8; i++) a[i] = As[(row0 + i) * AS_LD + kk];
            *reinterpret_cast<float4*>(&b[0]) = *reinterpret_cast<float4*>(Bs + kk * 128 + col0);
            *reinterpret_cast<float4*>(&b[4]) = *reinterpret_cast<float4*>(Bs + kk * 128 + col0 + 4);
#pragma unroll
            for (int i = 0; i < 8; i++)
#pragma unroll
                for (int j = 0; j < 8; j++) c[i][j] += a[i] * b[j];
        }
        __syncthreads();
    }
    // bias + ELU -> Hs
#pragma unroll
    for (int i = 0; i < 8; i++) {
        float t[8];
#pragma unroll
        for (int j = 0; j < 8; j++) {
            const float v = c[i][j] + b0[col0 + j];
            t[j] = v > 0.f ? v : expm1f(v);
        }
        *reinterpret_cast<float4*>(Hs + (row0 + i) * HS_LD + col0)     = make_float4(t[0], t[1], t[2], t[3]);
        *reinterpret_cast<float4*>(Hs + (row0 + i) * HS_LD + col0 + 4) = make_float4(t[4], t[5], t[6], t[7]);
    }
    __syncthreads();

    // ================= Layer 1: Hs @ W2 =================
#pragma unroll
    for (int i = 0; i < 8; i++)
#pragma unroll
        for (int j = 0; j < 8; j++) c[i][j] = 0.f;

    for (int k0 = 0; k0 < HID; k0 += 32) {
#pragma unroll
        for (int l = tid; l < 1024; l += 256) {
            const int kr = l >> 5, c4 = l & 31;
            *reinterpret_cast<float4*>(Bs + kr * 128 + c4 * 4) =
                *reinterpret_cast<const float4*>(W2 + (size_t)(k0 + kr) * 128 + c4 * 4);
        }
        __syncthreads();
#pragma unroll
        for (int kk = 0; kk < 32; kk++) {
            float a[8], b[8];
#pragma unroll
            for (int i = 0; i < 8; i++) a[i] = Hs[(row0 + i) * HS_LD + k0 + kk];
            *reinterpret_cast<float4*>(&b[0]) = *reinterpret_cast<float4*>(Bs + kk * 128 + col0);
            *reinterpret_cast<float4*>(&b[4]) = *reinterpret_cast<float4*>(Bs + kk * 128 + col0 + 4);
#pragma unroll
            for (int i = 0; i < 8; i++)
#pragma unroll
                for (int j = 0; j < 8; j++) c[i][j] += a[i] * b[j];
        }
        __syncthreads();
    }
    {
        // bias + ELU -> Hs (all reads of Hs finished: sync above)
        float t[8][8];
#pragma unroll
        for (int i = 0; i < 8; i++)
#pragma unroll
            for (int j = 0; j < 8; j++) {
                const float v = c[i][j] + b2[col0 + j];
                t[i][j] = v > 0.f ? v : expm1f(v);
            }
        __syncthreads();
#pragma unroll
        for (int i = 0; i < 8; i++) {
            *reinterpret_cast<float4*>(Hs + (row0 + i) * HS_LD + col0)     = make_float4(t[i][0], t[i][1], t[i][2], t[i][3]);
            *reinterpret_cast<float4*>(Hs + (row0 + i) * HS_LD + col0 + 4) = make_float4(t[i][4], t[i][5], t[i][6], t[i][7]);
        }
        __syncthreads();
    }

    // ================= Layer 2: Hs @ W3 -> out =================
#pragma unroll
    for (int i = 0; i < 8; i++)
#pragma unroll
        for (int j = 0; j < 8; j++) c[i][j] = 0.f;

    for (int k0 = 0; k0 < HID; k0 += 32) {
#pragma unroll
        for (int l = tid; l < 1024; l += 256) {
            const int kr = l >> 5, c4 = l & 31;
            *reinterpret_cast<float4*>(Bs + kr * 128 + c4 * 4) =
                *reinterpret_cast<const float4*>(W3 + (size_t)(k0 + kr) * 128 + c4 * 4);
        }
        __syncthreads();
#pragma unroll
        for (int kk = 0; kk < 32; kk++) {
            float a[8], b[8];
#pragma unroll
            for (int i = 0; i < 8; i++) a[i] = Hs[(row0 + i) * HS_LD + k0 + kk];
            *reinterpret_cast<float4*>(&b[0]) = *reinterpret_cast<float4*>(Bs + kk * 128 + col0);
            *reinterpret_cast<float4*>(&b[4]) = *reinterpret_cast<float4*>(Bs + kk * 128 + col0 + 4);
#pragma unroll
            for (int i = 0; i < 8; i++)
#pragma unroll
                for (int j = 0; j < 8; j++) c[i][j] += a[i] * b[j];
        }
        __syncthreads();
    }
#pragma unroll
    for (int i = 0; i < 8; i++) {
        const int gn = nodeBase + row0 + i;
        if (gn < N_NODES) {
            float t[8];
#pragma unroll
            for (int j = 0; j < 8; j++) t[j] = c[i][j] + b3[col0 + j];
            *reinterpret_cast<float4*>(out + (size_t)gn * OUTCH + col0)     = make_float4(t[0], t[1], t[2], t[3]);
            *reinterpret_cast<float4*>(out + (size_t)gn * OUTCH + col0 + 4) = make_float4(t[4], t[5], t[6], t[7]);
        }
    }
}

// ---------------------------------------------------------------------------
extern "C" void kernel_launch(void* const* d_in, const int* in_sizes, int n_in,
                              void* d_out, int out_size) {
    (void)in_sizes; (void)n_in; (void)out_size;
    const float* x          = (const float*)d_in[0];
    const int*   edge_index = (const int*)d_in[1];    // [2, E] int32 (JAX x64 disabled)
    const float* edge_attr  = (const float*)d_in[2];
    const float* W0 = (const float*)d_in[3];
    const float* b0 = (const float*)d_in[4];
    const float* W2 = (const float*)d_in[5];
    const float* b2 = (const float*)d_in[6];
    const float* W3 = (const float*)d_in[7];
    const float* b3 = (const float*)d_in[8];
    float* out = (float*)d_out;

    static bool attr_set = false;
    if (!attr_set) {
        cudaFuncSetAttribute(mlp_kernel, cudaFuncAttributeMaxDynamicSharedMemorySize,
                             SMEM_FLOATS * (int)sizeof(float));
        attr_set = true;
    }

    zero_kernel<<<2048, 256>>>();

    const int scatter_blocks = (N_EDGES * 32 + 255) / 256;  // 1 warp/edge
    scatter_kernel<<<scatter_blocks, 256>>>(edge_attr, edge_index);

    const int mlp_blocks = (N_NODES + 127) / 128;           // 391
    mlp_kernel<<<mlp_blocks, 256, SMEM_FLOATS * (int)sizeof(float)>>>(
        x, W0, b0, W2, b2, W3, b3, out);
}

// round 3
// speedup vs baseline: 1.8249x; 1.8249x over previous
#include <cuda_runtime.h>
#include <cstdint>
#include <math.h>

#define N_NODES 50000
#define N_EDGES 800000
#define XD      128
#define HID     128
#define INCH    256
#define OUTCH   128

__device__ float g_edge_sum[(size_t)N_NODES * HID];

// ---------------------------------------------------------------------------
// Kernel 1: zero accumulator
// ---------------------------------------------------------------------------
__global__ void zero_kernel() {
    const size_t n4 = (size_t)N_NODES * HID / 4;
    float4* p = reinterpret_cast<float4*>(g_edge_sum);
    for (size_t i = (size_t)blockIdx.x * blockDim.x + threadIdx.x; i < n4;
         i += (size_t)gridDim.x * blockDim.x) {
        p[i] = make_float4(0.f, 0.f, 0.f, 0.f);
    }
}

// ---------------------------------------------------------------------------
// Kernel 2: scatter-add edge rows (1 warp/edge, red.global.add.v4.f32)
// ---------------------------------------------------------------------------
__global__ void scatter_kernel(const float* __restrict__ edge_attr,
                               const int* __restrict__ edge_src) {
    const int warp = (blockIdx.x * blockDim.x + threadIdx.x) >> 5;
    const int lane = threadIdx.x & 31;
    if (warp >= N_EDGES) return;
    const int src = edge_src[warp];
    const float4 v = reinterpret_cast<const float4*>(edge_attr + (size_t)warp * HID)[lane];
    float* dst = g_edge_sum + (size_t)src * HID + lane * 4;
    asm volatile("red.global.add.v4.f32 [%0], {%1,%2,%3,%4};"
                 :: "l"(dst), "f"(v.x), "f"(v.y), "f"(v.z), "f"(v.w)
                 : "memory");
}

// ---------------------------------------------------------------------------
// Kernel 3: fused 3-layer MLP on tf32 tensor cores (mma.sync.m16n8k8).
// CTA tile: 128 nodes x 128 cols, 256 threads = 8 warps in 4x2 (M x N) grid;
// warp tile 32 x 64 -> 2 m-frags x 8 n-frags of m16n8k8.
// SMEM: Hs[128][132] (activations, tf32 bits), As[128][36] (layer-0 input
// chunk), Bs[32][132] (weight chunk). All A-frag LDS conflict-free; B-frag
// <=2-way. fp32 accumulate; inputs rounded via cvt.rna.tf32.f32.
// ---------------------------------------------------------------------------
#define HS_LD 132
#define AS_LD 36
#define BS_LD 132
#define SMEM_FLOATS (128*HS_LD + 128*AS_LD + 32*BS_LD)

__device__ __forceinline__ uint32_t f2tf(float f) {
    uint32_t u;
    asm("cvt.rna.tf32.f32 %0, %1;" : "=r"(u) : "f"(f));
    return u;
}

__device__ __forceinline__ void mma_tf32(float c[4], const uint32_t a[4],
                                         uint32_t b0, uint32_t b1) {
    asm volatile(
        "mma.sync.aligned.m16n8k8.row.col.f32.tf32.tf32.f32 "
        "{%0,%1,%2,%3}, {%4,%5,%6,%7}, {%8,%9}, {%0,%1,%2,%3};"
        : "+f"(c[0]), "+f"(c[1]), "+f"(c[2]), "+f"(c[3])
        : "r"(a[0]), "r"(a[1]), "r"(a[2]), "r"(a[3]), "r"(b0), "r"(b1));
}

__global__ __launch_bounds__(256, 2)
void mlp_kernel(const float* __restrict__ x,
                const float* __restrict__ W0, const float* __restrict__ b0v,
                const float* __restrict__ W2, const float* __restrict__ b2v,
                const float* __restrict__ W3, const float* __restrict__ b3v,
                float* __restrict__ out) {
    extern __shared__ float sm[];
    float* Hs = sm;                        // 128 x 132 (tf32 bit patterns)
    float* As = sm + 128 * HS_LD;          // 128 x 36
    float* Bs = As + 128 * AS_LD;          // 32 x 132
    uint32_t* Hsu = reinterpret_cast<uint32_t*>(Hs);
    uint32_t* Asu = reinterpret_cast<uint32_t*>(As);
    uint32_t* Bsu = reinterpret_cast<uint32_t*>(Bs);

    const int tid  = threadIdx.x;
    const int lane = tid & 31;
    const int wid  = tid >> 5;
    const int gi   = lane >> 2;            // group id (0..7)
    const int ti   = lane & 3;             // thread-in-group (0..3)
    const int warp_m = (wid & 3) * 32;     // 4 warps along M
    const int warp_n = (wid >> 2) * 64;    // 2 warps along N
    const int nodeBase = blockIdx.x * 128;

    float c[2][8][4];

    // =============== Layer 0: [128 x 256] @ W0[256 x 128] ===============
#pragma unroll
    for (int mf = 0; mf < 2; mf++)
#pragma unroll
        for (int nf = 0; nf < 8; nf++)
#pragma unroll
            for (int r = 0; r < 4; r++) c[mf][nf][r] = 0.f;

    for (int k0 = 0; k0 < INCH; k0 += 32) {
        const float* srcA = (k0 < XD) ? x : g_edge_sum;
        const int kcol = k0 & (XD - 1);
        // Stage A chunk [128 x 32] (tf32-rounded)
#pragma unroll
        for (int l = tid; l < 1024; l += 256) {
            const int node = l >> 3, k4 = l & 7;
            float4 v = make_float4(0.f, 0.f, 0.f, 0.f);
            const int gn = nodeBase + node;
            if (gn < N_NODES)
                v = *reinterpret_cast<const float4*>(srcA + (size_t)gn * 128 + kcol + k4 * 4);
            uint32_t* d = Asu + node * AS_LD + k4 * 4;
            d[0] = f2tf(v.x); d[1] = f2tf(v.y); d[2] = f2tf(v.z); d[3] = f2tf(v.w);
        }
        // Stage B chunk [32 x 128] (tf32-rounded)
#pragma unroll
        for (int l = tid; l < 1024; l += 256) {
            const int kr = l >> 5, c4 = l & 31;
            float4 v = *reinterpret_cast<const float4*>(W0 + (size_t)(k0 + kr) * 128 + c4 * 4);
            uint32_t* d = Bsu + kr * BS_LD + c4 * 4;
            d[0] = f2tf(v.x); d[1] = f2tf(v.y); d[2] = f2tf(v.z); d[3] = f2tf(v.w);
        }
        __syncthreads();
#pragma unroll
        for (int kk = 0; kk < 32; kk += 8) {
            uint32_t a[2][4];
#pragma unroll
            for (int mf = 0; mf < 2; mf++) {
                const int r = warp_m + mf * 16 + gi;
                a[mf][0] = Asu[r * AS_LD + kk + ti];
                a[mf][1] = Asu[(r + 8) * AS_LD + kk + ti];
                a[mf][2] = Asu[r * AS_LD + kk + ti + 4];
                a[mf][3] = Asu[(r + 8) * AS_LD + kk + ti + 4];
            }
#pragma unroll
            for (int nf = 0; nf < 8; nf++) {
                const int nc = warp_n + nf * 8 + gi;
                const uint32_t bb0 = Bsu[(kk + ti) * BS_LD + nc];
                const uint32_t bb1 = Bsu[(kk + ti + 4) * BS_LD + nc];
                mma_tf32(c[0][nf], a[0], bb0, bb1);
                mma_tf32(c[1][nf], a[1], bb0, bb1);
            }
        }
        __syncthreads();
    }
    // bias + ELU -> Hs (tf32-rounded)
#pragma unroll
    for (int mf = 0; mf < 2; mf++)
#pragma unroll
        for (int nf = 0; nf < 8; nf++) {
            const int row = warp_m + mf * 16 + gi;
            const int col = warp_n + nf * 8 + 2 * ti;
            const float bi0 = b0v[col], bi1 = b0v[col + 1];
            float v0 = c[mf][nf][0] + bi0, v1 = c[mf][nf][1] + bi1;
            float v2 = c[mf][nf][2] + bi0, v3 = c[mf][nf][3] + bi1;
            v0 = v0 > 0.f ? v0 : expm1f(v0);
            v1 = v1 > 0.f ? v1 : expm1f(v1);
            v2 = v2 > 0.f ? v2 : expm1f(v2);
            v3 = v3 > 0.f ? v3 : expm1f(v3);
            Hsu[row * HS_LD + col]           = f2tf(v0);
            Hsu[row * HS_LD + col + 1]       = f2tf(v1);
            Hsu[(row + 8) * HS_LD + col]     = f2tf(v2);
            Hsu[(row + 8) * HS_LD + col + 1] = f2tf(v3);
        }
    __syncthreads();

    // =============== Layer 1: Hs @ W2 ===============
#pragma unroll
    for (int mf = 0; mf < 2; mf++)
#pragma unroll
        for (int nf = 0; nf < 8; nf++)
#pragma unroll
            for (int r = 0; r < 4; r++) c[mf][nf][r] = 0.f;

    for (int k0 = 0; k0 < HID; k0 += 32) {
#pragma unroll
        for (int l = tid; l < 1024; l += 256) {
            const int kr = l >> 5, c4 = l & 31;
            float4 v = *reinterpret_cast<const float4*>(W2 + (size_t)(k0 + kr) * 128 + c4 * 4);
            uint32_t* d = Bsu + kr * BS_LD + c4 * 4;
            d[0] = f2tf(v.x); d[1] = f2tf(v.y); d[2] = f2tf(v.z); d[3] = f2tf(v.w);
        }
        __syncthreads();
#pragma unroll
        for (int kk = 0; kk < 32; kk += 8) {
            uint32_t a[2][4];
#pragma unroll
            for (int mf = 0; mf < 2; mf++) {
                const int r = warp_m + mf * 16 + gi;
                const int kc = k0 + kk + ti;
                a[mf][0] = Hsu[r * HS_LD + kc];
                a[mf][1] = Hsu[(r + 8) * HS_LD + kc];
                a[mf][2] = Hsu[r * HS_LD + kc + 4];
                a[mf][3] = Hsu[(r + 8) * HS_LD + kc + 4];
            }
#pragma unroll
            for (int nf = 0; nf < 8; nf++) {
                const int nc = warp_n + nf * 8 + gi;
                const uint32_t bb0 = Bsu[(kk + ti) * BS_LD + nc];
                const uint32_t bb1 = Bsu[(kk + ti + 4) * BS_LD + nc];
                mma_tf32(c[0][nf], a[0], bb0, bb1);
                mma_tf32(c[1][nf], a[1], bb0, bb1);
            }
        }
        __syncthreads();
    }
    // bias + ELU -> Hs (all reads done: sync above)
#pragma unroll
    for (int mf = 0; mf < 2; mf++)
#pragma unroll
        for (int nf = 0; nf < 8; nf++) {
            const int row = warp_m + mf * 16 + gi;
            const int col = warp_n + nf * 8 + 2 * ti;
            const float bi0 = b2v[col], bi1 = b2v[col + 1];
            float v0 = c[mf][nf][0] + bi0, v1 = c[mf][nf][1] + bi1;
            float v2 = c[mf][nf][2] + bi0, v3 = c[mf][nf][3] + bi1;
            v0 = v0 > 0.f ? v0 : expm1f(v0);
            v1 = v1 > 0.f ? v1 : expm1f(v1);
            v2 = v2 > 0.f ? v2 : expm1f(v2);
            v3 = v3 > 0.f ? v3 : expm1f(v3);
            Hsu[row * HS_LD + col]           = f2tf(v0);
            Hsu[row * HS_LD + col + 1]       = f2tf(v1);
            Hsu[(row + 8) * HS_LD + col]     = f2tf(v2);
            Hsu[(row + 8) * HS_LD + col + 1] = f2tf(v3);
        }
    __syncthreads();

    // =============== Layer 2: Hs @ W3 -> out ===============
#pragma unroll
    for (int mf = 0; mf < 2; mf++)
#pragma unroll
        for (int nf = 0; nf < 8; nf++)
#pragma unroll
            for (int r = 0; r < 4; r++) c[mf][nf][r] = 0.f;

    for (int k0 = 0; k0 < HID; k0 += 32) {
#pragma unroll
        for (int l = tid; l < 1024; l += 256) {
            const int kr = l >> 5, c4 = l & 31;
            float4 v = *reinterpret_cast<const float4*>(W3 + (size_t)(k0 + kr) * 128 + c4 * 4);
            uint32_t* d = Bsu + kr * BS_LD + c4 * 4;
            d[0] = f2tf(v.x); d[1] = f2tf(v.y); d[2] = f2tf(v.z); d[3] = f2tf(v.w);
        }
        __syncthreads();
#pragma unroll
        for (int kk = 0; kk < 32; kk += 8) {
            uint32_t a[2][4];
#pragma unroll
            for (int mf = 0; mf < 2; mf++) {
                const int r = warp_m + mf * 16 + gi;
                const int kc = k0 + kk + ti;
                a[mf][0] = Hsu[r * HS_LD + kc];
                a[mf][1] = Hsu[(r + 8) * HS_LD + kc];
                a[mf][2] = Hsu[r * HS_LD + kc + 4];
                a[mf][3] = Hsu[(r + 8) * HS_LD + kc + 4];
            }
#pragma unroll
            for (int nf = 0; nf < 8; nf++) {
                const int nc = warp_n + nf * 8 + gi;
                const uint32_t bb0 = Bsu[(kk + ti) * BS_LD + nc];
                const uint32_t bb1 = Bsu[(kk + ti + 4) * BS_LD + nc];
                mma_tf32(c[0][nf], a[0], bb0, bb1);
                mma_tf32(c[1][nf], a[1], bb0, bb1);
            }
        }
        __syncthreads();
    }
    // bias -> gmem
#pragma unroll
    for (int mf = 0; mf < 2; mf++) {
        const int row = warp_m + mf * 16 + gi;
        const int gn0 = nodeBase + row;
        const int gn1 = gn0 + 8;
#pragma unroll
        for (int nf = 0; nf < 8; nf++) {
            const int col = warp_n + nf * 8 + 2 * ti;
            const float bi0 = b3v[col], bi1 = b3v[col + 1];
            if (gn0 < N_NODES)
                *reinterpret_cast<float2*>(out + (size_t)gn0 * OUTCH + col) =
                    make_float2(c[mf][nf][0] + bi0, c[mf][nf][1] + bi1);
            if (gn1 < N_NODES)
                *reinterpret_cast<float2*>(out + (size_t)gn1 * OUTCH + col) =
                    make_float2(c[mf][nf][2] + bi0, c[mf][nf][3] + bi1);
        }
    }
}

// ---------------------------------------------------------------------------
extern "C" void kernel_launch(void* const* d_in, const int* in_sizes, int n_in,
                              void* d_out, int out_size) {
    (void)in_sizes; (void)n_in; (void)out_size;
    const float* x          = (const float*)d_in[0];
    const int*   edge_index = (const int*)d_in[1];    // [2, E] int32
    const float* edge_attr  = (const float*)d_in[2];
    const float* W0 = (const float*)d_in[3];
    const float* b0 = (const float*)d_in[4];
    const float* W2 = (const float*)d_in[5];
    const float* b2 = (const float*)d_in[6];
    const float* W3 = (const float*)d_in[7];
    const float* b3 = (const float*)d_in[8];
    float* out = (float*)d_out;

    static bool attr_set = false;
    if (!attr_set) {
        cudaFuncSetAttribute(mlp_kernel, cudaFuncAttributeMaxDynamicSharedMemorySize,
                             SMEM_FLOATS * (int)sizeof(float));
        attr_set = true;
    }

    zero_kernel<<<2048, 256>>>();

    const int scatter_blocks = (N_EDGES * 32 + 255) / 256;
    scatter_kernel<<<scatter_blocks, 256>>>(edge_attr, edge_index);

    const int mlp_blocks = (N_NODES + 127) / 128;
    mlp_kernel<<<mlp_blocks, 256, SMEM_FLOATS * (int)sizeof(float)>>>(
        x, W0, b0, W2, b2, W3, b3, out);
}